// round 2
// baseline (speedup 1.0000x reference)
#include <cuda_runtime.h>
#include <math.h>

// Problem dims
#define B_  16
#define C_  256
#define H_  128
#define W_  128
#define HW  (H_ * W_)         // 16384
#define HW4 (HW / 4)          // 4096 float4 per plane

// Device scratch (no allocation allowed)
__device__ float g_m[B_ * HW];        // channel-mean map [b][h][w]
__device__ float g_cf[B_ * C_];       // sigmoid gate [b][c]
__device__ float g_Pt[B_ * HW];       // (C*m) transposed: [b][w][u]
__device__ float g_Qt[B_ * HW];       // (S*m) transposed: [b][w][u]
__device__ float g_sf[B_ * HW];       // sf [b][h][w]

// ---------------------------------------------------------------------------
// Kernel 1: m[b,h,w] = (1/256) * sum_c x[b,c,h,w]      (float4 over w)
// ---------------------------------------------------------------------------
__global__ void mean_kernel(const float4* __restrict__ x) {
    int t = blockIdx.x * 256 + threadIdx.x;            // 0 .. 65535
    int b = t >> 12;
    int pos = t & 4095;
    const float4* p = x + (size_t)b * C_ * HW4 + pos;
    float4 a0 = make_float4(0.f, 0.f, 0.f, 0.f);
    float4 a1 = make_float4(0.f, 0.f, 0.f, 0.f);
#pragma unroll 8
    for (int c = 0; c < C_; c += 2) {
        float4 v0 = __ldcs(&p[(size_t)c * HW4]);
        float4 v1 = __ldcs(&p[(size_t)(c + 1) * HW4]);
        a0.x += v0.x; a0.y += v0.y; a0.z += v0.z; a0.w += v0.w;
        a1.x += v1.x; a1.y += v1.y; a1.z += v1.z; a1.w += v1.w;
    }
    const float s = 1.0f / 256.0f;
    float4 acc;
    acc.x = (a0.x + a1.x) * s;
    acc.y = (a0.y + a1.y) * s;
    acc.z = (a0.z + a1.z) * s;
    acc.w = (a0.w + a1.w) * s;
    ((float4*)g_m)[t] = acc;
}

// ---------------------------------------------------------------------------
// Kernel 2: cf[b,c] = sigmoid( sum_k x[b,k,0,0] * W[c,k] + bias[c] )
// ---------------------------------------------------------------------------
__global__ void cf_kernel(const float* __restrict__ x,
                          const float* __restrict__ Wm,
                          const float* __restrict__ bias) {
    __shared__ __align__(16) float xs[C_];
    int b = blockIdx.x;
    int c = threadIdx.x;
    xs[c] = x[((size_t)(b * C_ + c)) * HW];   // x[b,c,0,0]
    __syncthreads();

    float acc = bias[c];
    const float4* wr = (const float4*)(Wm + (size_t)c * C_);
    const float4* xv = (const float4*)xs;
#pragma unroll 8
    for (int k = 0; k < C_ / 4; ++k) {
        float4 w4 = wr[k];
        float4 x4 = xv[k];
        acc += w4.x * x4.x + w4.y * x4.y + w4.z * x4.z + w4.w * x4.w;
    }
    g_cf[b * C_ + c] = 1.0f / (1.0f + expf(-acc));
}

// ---------------------------------------------------------------------------
// DFT stages: twiddles via per-thread complex rotation recurrence.
// Tile = 4 columns -> grid (32, 16) = 512 blocks, 256 threads
// = 128 rows (per-lane) x 2 colgroups of 2 cols. Shared reads broadcast.
// Outputs stored transposed (coalesced over 128-lane row index).
// ---------------------------------------------------------------------------
__global__ void dft_stage1(void) {
    __shared__ __align__(16) float2 ms[128 * 2];   // [h][colgroup]

    int b  = blockIdx.y;
    int wt = blockIdx.x;           // w-tile (4 wide)
    int tid = threadIdx.x;
    int u  = tid & 127;
    int wg = tid >> 7;

    {
        const float* mb = g_m + (size_t)b * HW + wt * 4;
        int h = tid >> 1, part = tid & 1;
        ms[h * 2 + part] = make_float2(mb[h * W_ + part * 2],
                                       mb[h * W_ + part * 2 + 1]);
    }
    __syncthreads();

    float su, cu;
    sincospif((float)u * (1.0f / 64.0f), &su, &cu);  // e^{i*2pi*u/128}
    float c = 1.0f, s = 0.0f;
    float2 aP = make_float2(0.f, 0.f);
    float2 aQ = make_float2(0.f, 0.f);
#pragma unroll 8
    for (int h = 0; h < 128; ++h) {
        float2 mm = ms[h * 2 + wg];
        aP.x += c * mm.x; aP.y += c * mm.y;
        aQ.x += s * mm.x; aQ.y += s * mm.y;
        float cn = c * cu - s * su;
        s = s * cu + c * su;
        c = cn;
    }
    size_t base = (size_t)b * HW;
    int w0 = wt * 4 + wg * 2;
    g_Pt[base + (w0 + 0) * 128 + u] = aP.x;
    g_Pt[base + (w0 + 1) * 128 + u] = aP.y;
    g_Qt[base + (w0 + 0) * 128 + u] = aQ.x;
    g_Qt[base + (w0 + 1) * 128 + u] = aQ.y;
}

__global__ void dft_stage2(void) {
    __shared__ __align__(16) float2 ps[128 * 2];
    __shared__ __align__(16) float2 qs[128 * 2];

    int b  = blockIdx.y;
    int ut = blockIdx.x;            // u-tile (4 wide)
    int tid = threadIdx.x;
    int v  = tid & 127;
    int ug = tid >> 7;

    {
        const float* pb = g_Pt + (size_t)b * HW + ut * 4;
        const float* qb = g_Qt + (size_t)b * HW + ut * 4;
        int w = tid >> 1, part = tid & 1;
        ps[w * 2 + part] = make_float2(pb[w * 128 + part * 2],
                                       pb[w * 128 + part * 2 + 1]);
        qs[w * 2 + part] = make_float2(qb[w * 128 + part * 2],
                                       qb[w * 128 + part * 2 + 1]);
    }
    __syncthreads();

    float sv, cv;
    sincospif((float)v * (1.0f / 64.0f), &sv, &cv);
    float c = 1.0f, s = 0.0f;
    float2 acc = make_float2(0.f, 0.f);
#pragma unroll 8
    for (int w = 0; w < 128; ++w) {
        float2 pp = ps[w * 2 + ug];
        float2 qq = qs[w * 2 + ug];
        acc.x += c * pp.x - s * qq.x;
        acc.y += c * pp.y - s * qq.y;
        float cn = c * cv - s * sv;
        s = s * cv + c * sv;
        c = cn;
    }
    size_t base = (size_t)b * HW;
    int u0 = ut * 4 + ug * 2;
    g_sf[base + (u0 + 0) * 128 + v] = acc.x;   // coalesced in v
    g_sf[base + (u0 + 1) * 128 + v] = acc.y;
}

// ---------------------------------------------------------------------------
// Kernel 4: out[b,c,h,w] = x[b,c,h,w] * (cf[b,c] + sf[b,h,w])
// 4 float4 per thread, front-batched loads, streaming hints.
// ---------------------------------------------------------------------------
__global__ void out_kernel(const float4* __restrict__ x, float4* __restrict__ out) {
    int t = blockIdx.x * 256 + threadIdx.x;
    int i0 = t * 4;                             // 4 consecutive float4, same plane
    int plane = i0 >> 12;
    int pos = i0 & 4095;
    int b = plane >> 8;
    float cf = g_cf[plane];
    const float4* sf4 = (const float4*)g_sf + b * HW4 + pos;

    float4 v0 = __ldcs(x + i0 + 0);
    float4 v1 = __ldcs(x + i0 + 1);
    float4 v2 = __ldcs(x + i0 + 2);
    float4 v3 = __ldcs(x + i0 + 3);
    float4 f0 = sf4[0];
    float4 f1 = sf4[1];
    float4 f2 = sf4[2];
    float4 f3 = sf4[3];

    float4 o0, o1, o2, o3;
    o0.x = v0.x * (cf + f0.x); o0.y = v0.y * (cf + f0.y);
    o0.z = v0.z * (cf + f0.z); o0.w = v0.w * (cf + f0.w);
    o1.x = v1.x * (cf + f1.x); o1.y = v1.y * (cf + f1.y);
    o1.z = v1.z * (cf + f1.z); o1.w = v1.w * (cf + f1.w);
    o2.x = v2.x * (cf + f2.x); o2.y = v2.y * (cf + f2.y);
    o2.z = v2.z * (cf + f2.z); o2.w = v2.w * (cf + f2.w);
    o3.x = v3.x * (cf + f3.x); o3.y = v3.y * (cf + f3.y);
    o3.z = v3.z * (cf + f3.z); o3.w = v3.w * (cf + f3.w);

    __stcs(out + i0 + 0, o0);
    __stcs(out + i0 + 1, o1);
    __stcs(out + i0 + 2, o2);
    __stcs(out + i0 + 3, o3);
}

extern "C" void kernel_launch(void* const* d_in, const int* in_sizes, int n_in,
                              void* d_out, int out_size) {
    const float* x    = (const float*)d_in[0];   // [16,256,128,128]
    const float* Wm   = (const float*)d_in[1];   // [256,256]
    const float* bias = (const float*)d_in[2];   // [256]
    float* out = (float*)d_out;

    cf_kernel<<<B_, C_>>>(x, Wm, bias);
    mean_kernel<<<(B_ * HW4) / 256, 256>>>((const float4*)x);
    dft_stage1<<<dim3(32, B_), 256>>>();
    dft_stage2<<<dim3(32, B_), 256>>>();
    out_kernel<<<(B_ * C_ * HW4) / (256 * 4), 256>>>((const float4*)x, (float4*)out);
}

// round 3
// speedup vs baseline: 1.1807x; 1.1807x over previous
#include <cuda_runtime.h>
#include <math.h>

// Problem dims
#define B_  16
#define C_  256
#define H_  128
#define W_  128
#define HW  (H_ * W_)         // 16384
#define HW4 (HW / 4)          // 4096 float4 per plane

// Device scratch (no allocation allowed)
__device__ float g_m[B_ * HW];        // channel-mean map [b][h][w]
__device__ float g_cf[B_ * C_];       // sigmoid gate [b][c]
__device__ float g_Pt[B_ * HW];       // (C*m) transposed: [b][w][u]
__device__ float g_Qt[B_ * HW];       // (S*m) transposed: [b][w][u]
__device__ float g_sf[B_ * HW];       // sf [b][h][w]

// ---------------------------------------------------------------------------
// Kernel 1: m[b,h,w] = (1/256) * sum_c x[b,c,h,w]   (1 float4/thread, coalesced)
// ---------------------------------------------------------------------------
__global__ void mean_kernel(const float4* __restrict__ x) {
    int t = blockIdx.x * 256 + threadIdx.x;            // 0 .. 65535
    int b = t >> 12;
    int pos = t & 4095;
    const float4* p = x + (size_t)b * C_ * HW4 + pos;
    float4 a0 = make_float4(0.f, 0.f, 0.f, 0.f);
    float4 a1 = make_float4(0.f, 0.f, 0.f, 0.f);
#pragma unroll 4
    for (int c = 0; c < C_; c += 2) {
        float4 v0 = __ldcs(&p[(size_t)c * HW4]);
        float4 v1 = __ldcs(&p[(size_t)(c + 1) * HW4]);
        a0.x += v0.x; a0.y += v0.y; a0.z += v0.z; a0.w += v0.w;
        a1.x += v1.x; a1.y += v1.y; a1.z += v1.z; a1.w += v1.w;
    }
    const float s = 1.0f / 256.0f;
    float4 acc;
    acc.x = (a0.x + a1.x) * s;
    acc.y = (a0.y + a1.y) * s;
    acc.z = (a0.z + a1.z) * s;
    acc.w = (a0.w + a1.w) * s;
    ((float4*)g_m)[t] = acc;
}

// ---------------------------------------------------------------------------
// Kernel 2: cf[b,c] = sigmoid( sum_k x[b,k,0,0] * W[c,k] + bias[c] )
// ---------------------------------------------------------------------------
__global__ void cf_kernel(const float* __restrict__ x,
                          const float* __restrict__ Wm,
                          const float* __restrict__ bias) {
    __shared__ __align__(16) float xs[C_];
    int b = blockIdx.x;
    int c = threadIdx.x;
    xs[c] = x[((size_t)(b * C_ + c)) * HW];   // x[b,c,0,0]
    __syncthreads();

    float acc = bias[c];
    const float4* wr = (const float4*)(Wm + (size_t)c * C_);
    const float4* xv = (const float4*)xs;
#pragma unroll 8
    for (int k = 0; k < C_ / 4; ++k) {
        float4 w4 = wr[k];
        float4 x4 = xv[k];
        acc += w4.x * x4.x + w4.y * x4.y + w4.z * x4.z + w4.w * x4.w;
    }
    g_cf[b * C_ + c] = 1.0f / (1.0f + expf(-acc));
}

// ---------------------------------------------------------------------------
// DFT stages. Twiddles: per-thread register twiddles for offsets 0..7 plus a
// step-8 base rotation -> only 16 dependent updates instead of 128, and the 8
// in-group twiddles are independent 2-FMA reconstructions. No shared-table
// bank conflicts. Tile = 4 columns -> grid (32, 16) = 512 blocks, 256 threads
// = 128 rows x 2 colgroups of 2 cols. Shared data reads are warp-broadcast.
// Outputs stored transposed (coalesced over the 128-lane row index).
// ---------------------------------------------------------------------------
__global__ void dft_stage1(void) {
    __shared__ __align__(16) float2 ms[128 * 2];   // [h][colgroup]

    int b  = blockIdx.y;
    int wt = blockIdx.x;           // w-tile (4 wide)
    int tid = threadIdx.x;
    int u  = tid & 127;
    int wg = tid >> 7;

    {
        const float* mb = g_m + (size_t)b * HW + wt * 4;
        int h = tid >> 1, part = tid & 1;
        ms[h * 2 + part] = make_float2(mb[h * W_ + part * 2],
                                       mb[h * W_ + part * 2 + 1]);
    }
    __syncthreads();

    // offset twiddles e^{i*2pi*u*j/128}, j=0..7, and step-8 rotation
    float cj[8], sj[8];
    cj[0] = 1.0f; sj[0] = 0.0f;
#pragma unroll
    for (int j = 1; j < 8; ++j)
        sincospif((float)(u * j) * (1.0f / 64.0f), &sj[j], &cj[j]);
    float c8, s8;
    sincospif((float)u * (1.0f / 8.0f), &s8, &c8);

    float cb = 1.0f, sb = 0.0f;
    float2 aP = make_float2(0.f, 0.f);
    float2 aQ = make_float2(0.f, 0.f);
#pragma unroll
    for (int g = 0; g < 16; ++g) {
#pragma unroll
        for (int j = 0; j < 8; ++j) {
            float cw = cb * cj[j] - sb * sj[j];
            float sw = sb * cj[j] + cb * sj[j];
            float2 mm = ms[(g * 8 + j) * 2 + wg];
            aP.x += cw * mm.x; aP.y += cw * mm.y;
            aQ.x += sw * mm.x; aQ.y += sw * mm.y;
        }
        float cn = cb * c8 - sb * s8;
        sb = sb * c8 + cb * s8;
        cb = cn;
    }
    size_t base = (size_t)b * HW;
    int w0 = wt * 4 + wg * 2;
    g_Pt[base + (w0 + 0) * 128 + u] = aP.x;
    g_Pt[base + (w0 + 1) * 128 + u] = aP.y;
    g_Qt[base + (w0 + 0) * 128 + u] = aQ.x;
    g_Qt[base + (w0 + 1) * 128 + u] = aQ.y;
}

__global__ void dft_stage2(void) {
    __shared__ __align__(16) float2 ps[128 * 2];
    __shared__ __align__(16) float2 qs[128 * 2];

    int b  = blockIdx.y;
    int ut = blockIdx.x;            // u-tile (4 wide)
    int tid = threadIdx.x;
    int v  = tid & 127;
    int ug = tid >> 7;

    {
        const float* pb = g_Pt + (size_t)b * HW + ut * 4;
        const float* qb = g_Qt + (size_t)b * HW + ut * 4;
        int w = tid >> 1, part = tid & 1;
        ps[w * 2 + part] = make_float2(pb[w * 128 + part * 2],
                                       pb[w * 128 + part * 2 + 1]);
        qs[w * 2 + part] = make_float2(qb[w * 128 + part * 2],
                                       qb[w * 128 + part * 2 + 1]);
    }
    __syncthreads();

    float cj[8], sj[8];
    cj[0] = 1.0f; sj[0] = 0.0f;
#pragma unroll
    for (int j = 1; j < 8; ++j)
        sincospif((float)(v * j) * (1.0f / 64.0f), &sj[j], &cj[j]);
    float c8, s8;
    sincospif((float)v * (1.0f / 8.0f), &s8, &c8);

    float cb = 1.0f, sb = 0.0f;
    float2 acc = make_float2(0.f, 0.f);
#pragma unroll
    for (int g = 0; g < 16; ++g) {
#pragma unroll
        for (int j = 0; j < 8; ++j) {
            float cw = cb * cj[j] - sb * sj[j];
            float sw = sb * cj[j] + cb * sj[j];
            int w = g * 8 + j;
            float2 pp = ps[w * 2 + ug];
            float2 qq = qs[w * 2 + ug];
            acc.x += cw * pp.x - sw * qq.x;
            acc.y += cw * pp.y - sw * qq.y;
        }
        float cn = cb * c8 - sb * s8;
        sb = sb * c8 + cb * s8;
        cb = cn;
    }
    size_t base = (size_t)b * HW;
    int u0 = ut * 4 + ug * 2;
    g_sf[base + (u0 + 0) * 128 + v] = acc.x;   // coalesced in v
    g_sf[base + (u0 + 1) * 128 + v] = acc.y;
}

// ---------------------------------------------------------------------------
// Kernel 4: out[b,c,h,w] = x[b,c,h,w] * (cf[b,c] + sf[b,h,w])
// Block owns a 1024-float4 chunk of one plane; 4 coalesced float4 per thread
// at stride 256; all loads front-batched (MLP_p1 = 8).
// ---------------------------------------------------------------------------
__global__ void out_kernel(const float4* __restrict__ x, float4* __restrict__ out) {
    int base = blockIdx.x * 1024;               // chunk start (plane-aligned /4)
    int plane = base >> 12;                     // (b*256 + c), constant per block
    int b = plane >> 8;
    int t = threadIdx.x;
    float cf = g_cf[plane];
    const float4* sf4 = (const float4*)g_sf + b * HW4 + (base & 4095);

    float4 v0 = __ldcs(x + base + t);
    float4 v1 = __ldcs(x + base + 256 + t);
    float4 v2 = __ldcs(x + base + 512 + t);
    float4 v3 = __ldcs(x + base + 768 + t);
    float4 f0 = sf4[t];
    float4 f1 = sf4[256 + t];
    float4 f2 = sf4[512 + t];
    float4 f3 = sf4[768 + t];

    float4 o0, o1, o2, o3;
    o0.x = v0.x * (cf + f0.x); o0.y = v0.y * (cf + f0.y);
    o0.z = v0.z * (cf + f0.z); o0.w = v0.w * (cf + f0.w);
    o1.x = v1.x * (cf + f1.x); o1.y = v1.y * (cf + f1.y);
    o1.z = v1.z * (cf + f1.z); o1.w = v1.w * (cf + f1.w);
    o2.x = v2.x * (cf + f2.x); o2.y = v2.y * (cf + f2.y);
    o2.z = v2.z * (cf + f2.z); o2.w = v2.w * (cf + f2.w);
    o3.x = v3.x * (cf + f3.x); o3.y = v3.y * (cf + f3.y);
    o3.z = v3.z * (cf + f3.z); o3.w = v3.w * (cf + f3.w);

    __stcs(out + base + t, o0);
    __stcs(out + base + 256 + t, o1);
    __stcs(out + base + 512 + t, o2);
    __stcs(out + base + 768 + t, o3);
}

extern "C" void kernel_launch(void* const* d_in, const int* in_sizes, int n_in,
                              void* d_out, int out_size) {
    const float* x    = (const float*)d_in[0];   // [16,256,128,128]
    const float* Wm   = (const float*)d_in[1];   // [256,256]
    const float* bias = (const float*)d_in[2];   // [256]
    float* out = (float*)d_out;

    cf_kernel<<<B_, C_>>>(x, Wm, bias);
    mean_kernel<<<(B_ * HW4) / 256, 256>>>((const float4*)x);
    dft_stage1<<<dim3(32, B_), 256>>>();
    dft_stage2<<<dim3(32, B_), 256>>>();
    out_kernel<<<(B_ * C_ * HW4) / 1024, 256>>>((const float4*)x, (float4*)out);
}

// round 4
// speedup vs baseline: 1.2756x; 1.0804x over previous
#include <cuda_runtime.h>
#include <math.h>

// Problem dims
#define B_  16
#define C_  256
#define H_  128
#define W_  128
#define HW  (H_ * W_)         // 16384
#define HW4 (HW / 4)          // 4096 float4 per plane

// Device scratch (no allocation allowed)
__device__ float g_m[B_ * HW];        // channel-mean map [b][h][w]
__device__ float g_cf[B_ * C_];       // sigmoid gate [b][c]
__device__ float g_Pt[B_ * HW];       // (C*m) transposed: [b][w][u]
__device__ float g_Qt[B_ * HW];       // (S*m) transposed: [b][w][u]
__device__ float g_sf[B_ * HW];       // sf [b][h][w]

// ---------------------------------------------------------------------------
// Kernel 1 (merged): blocks 0..1023  -> channel mean (64 threads each)
//                    blocks 1024..1087 -> cf gate (sigmoid(x00 @ W^T + b))
// mean uses DEFAULT cache policy so the tail of x stays resident in L2 for
// out_kernel (which consumes it in reverse order).
// ---------------------------------------------------------------------------
__global__ void mean_cf_kernel(const float4* __restrict__ x,
                               const float* __restrict__ Wm,
                               const float* __restrict__ bias) {
    if (blockIdx.x < 1024) {
        int t = blockIdx.x * 64 + threadIdx.x;             // 0 .. 65535
        int b = t >> 12;
        int pos = t & 4095;
        const float4* p = x + (size_t)b * C_ * HW4 + pos;
        float4 a0 = make_float4(0.f, 0.f, 0.f, 0.f);
        float4 a1 = make_float4(0.f, 0.f, 0.f, 0.f);
#pragma unroll 8
        for (int c = 0; c < C_; c += 2) {
            float4 v0 = p[(size_t)c * HW4];
            float4 v1 = p[(size_t)(c + 1) * HW4];
            a0.x += v0.x; a0.y += v0.y; a0.z += v0.z; a0.w += v0.w;
            a1.x += v1.x; a1.y += v1.y; a1.z += v1.z; a1.w += v1.w;
        }
        const float s = 1.0f / 256.0f;
        float4 acc;
        acc.x = (a0.x + a1.x) * s;
        acc.y = (a0.y + a1.y) * s;
        acc.z = (a0.z + a1.z) * s;
        acc.w = (a0.w + a1.w) * s;
        ((float4*)g_m)[t] = acc;
    } else {
        // cf path: 64 blocks, block cb -> batch cb>>2, c range (cb&3)*64
        __shared__ __align__(16) float xs[C_];
        int cb = blockIdx.x - 1024;
        int b  = cb >> 2;
        int c0 = (cb & 3) * 64;
        const float* xf = (const float*)x;
#pragma unroll
        for (int k = 0; k < 4; ++k) {
            int ch = threadIdx.x * 4 + k;
            xs[ch] = xf[((size_t)(b * C_ + ch)) * HW];     // x[b,ch,0,0]
        }
        __syncthreads();
        int c = c0 + threadIdx.x;
        float acc = bias[c];
        const float4* wr = (const float4*)(Wm + (size_t)c * C_);
        const float4* xv = (const float4*)xs;
#pragma unroll 8
        for (int k = 0; k < C_ / 4; ++k) {
            float4 w4 = wr[k];
            float4 x4 = xv[k];
            acc += w4.x * x4.x + w4.y * x4.y + w4.z * x4.z + w4.w * x4.w;
        }
        g_cf[b * C_ + c] = 1.0f / (1.0f + expf(-acc));
    }
}

// ---------------------------------------------------------------------------
// DFT stages with h-fold symmetry (cos even / sin odd about the midpoint):
//   P[u] = m0 + cos(pi*u)*m64 + sum_{h=1..63} cos(2pi u h/128)*(m[h]+m[128-h])
//   Q[u] =                      sum_{h=1..63} sin(2pi u h/128)*(m[h]-m[128-h])
// Twiddles reconstructed from two 8-entry register tables (g = h>>3, j = h&7):
//   cw = cg[g]*cj[j] - sg[g]*sj[j]   (fully independent, no serial chain)
// Tile = 4 columns, grid (32, 16), 256 threads = 128 rows x 2 colgroups.
// Outputs stored transposed (coalesced over 128-lane row index).
// ---------------------------------------------------------------------------
__global__ void dft_stage1(void) {
    __shared__ __align__(16) float2 ms[128 * 2];   // [h][colgroup]

    int b  = blockIdx.y;
    int wt = blockIdx.x;           // w-tile (4 wide)
    int tid = threadIdx.x;
    int u  = tid & 127;
    int wg = tid >> 7;

    {
        const float* mb = g_m + (size_t)b * HW + wt * 4;
        int h = tid >> 1, part = tid & 1;
        ms[h * 2 + part] = make_float2(mb[h * W_ + part * 2],
                                       mb[h * W_ + part * 2 + 1]);
    }
    __syncthreads();

    float cj[8], sj[8], cg[8], sg[8];
    cj[0] = 1.0f; sj[0] = 0.0f;
    cg[0] = 1.0f; sg[0] = 0.0f;
#pragma unroll
    for (int j = 1; j < 8; ++j)
        sincospif((float)(u * j) * (1.0f / 64.0f), &sj[j], &cj[j]);
#pragma unroll
    for (int g = 1; g < 8; ++g)
        sincospif((float)(u * g) * (1.0f / 8.0f), &sg[g], &cg[g]);

    float2 m0  = ms[0 * 2 + wg];
    float2 m64 = ms[64 * 2 + wg];
    float sgn = (u & 1) ? -1.0f : 1.0f;
    float2 aP = make_float2(m0.x + sgn * m64.x, m0.y + sgn * m64.y);
    float2 aQ = make_float2(0.f, 0.f);

#pragma unroll
    for (int h = 1; h < 64; ++h) {
        int g = h >> 3, j = h & 7;
        float cw = cg[g] * cj[j] - sg[g] * sj[j];
        float sw = sg[g] * cj[j] + cg[g] * sj[j];
        float2 m1 = ms[h * 2 + wg];
        float2 m2 = ms[(128 - h) * 2 + wg];
        float2 me = make_float2(m1.x + m2.x, m1.y + m2.y);
        float2 mo = make_float2(m1.x - m2.x, m1.y - m2.y);
        aP.x += cw * me.x; aP.y += cw * me.y;
        aQ.x += sw * mo.x; aQ.y += sw * mo.y;
    }

    size_t base = (size_t)b * HW;
    int w0 = wt * 4 + wg * 2;
    g_Pt[base + (w0 + 0) * 128 + u] = aP.x;
    g_Pt[base + (w0 + 1) * 128 + u] = aP.y;
    g_Qt[base + (w0 + 0) * 128 + u] = aQ.x;
    g_Qt[base + (w0 + 1) * 128 + u] = aQ.y;
}

__global__ void dft_stage2(void) {
    __shared__ __align__(16) float2 ps[128 * 2];
    __shared__ __align__(16) float2 qs[128 * 2];

    int b  = blockIdx.y;
    int ut = blockIdx.x;            // u-tile (4 wide)
    int tid = threadIdx.x;
    int v  = tid & 127;
    int ug = tid >> 7;

    {
        const float* pb = g_Pt + (size_t)b * HW + ut * 4;
        const float* qb = g_Qt + (size_t)b * HW + ut * 4;
        int w = tid >> 1, part = tid & 1;
        ps[w * 2 + part] = make_float2(pb[w * 128 + part * 2],
                                       pb[w * 128 + part * 2 + 1]);
        qs[w * 2 + part] = make_float2(qb[w * 128 + part * 2],
                                       qb[w * 128 + part * 2 + 1]);
    }
    __syncthreads();

    float cj[8], sj[8], cg[8], sg[8];
    cj[0] = 1.0f; sj[0] = 0.0f;
    cg[0] = 1.0f; sg[0] = 0.0f;
#pragma unroll
    for (int j = 1; j < 8; ++j)
        sincospif((float)(v * j) * (1.0f / 64.0f), &sj[j], &cj[j]);
#pragma unroll
    for (int g = 1; g < 8; ++g)
        sincospif((float)(v * g) * (1.0f / 8.0f), &sg[g], &cg[g]);

    float2 p0  = ps[0 * 2 + ug];
    float2 p64 = ps[64 * 2 + ug];
    float sgn = (v & 1) ? -1.0f : 1.0f;
    float2 acc = make_float2(p0.x + sgn * p64.x, p0.y + sgn * p64.y);

#pragma unroll
    for (int w = 1; w < 64; ++w) {
        int g = w >> 3, j = w & 7;
        float cw = cg[g] * cj[j] - sg[g] * sj[j];
        float sw = sg[g] * cj[j] + cg[g] * sj[j];
        float2 pa = ps[w * 2 + ug];
        float2 pb2 = ps[(128 - w) * 2 + ug];
        float2 qa = qs[w * 2 + ug];
        float2 qb2 = qs[(128 - w) * 2 + ug];
        float2 pe = make_float2(pa.x + pb2.x, pa.y + pb2.y);
        float2 qo = make_float2(qa.x - qb2.x, qa.y - qb2.y);
        acc.x += cw * pe.x - sw * qo.x;
        acc.y += cw * pe.y - sw * qo.y;
    }

    size_t base = (size_t)b * HW;
    int u0 = ut * 4 + ug * 2;
    g_sf[base + (u0 + 0) * 128 + v] = acc.x;   // coalesced in v
    g_sf[base + (u0 + 1) * 128 + v] = acc.y;
}

// ---------------------------------------------------------------------------
// Kernel 4: out[b,c,h,w] = x[b,c,h,w] * (cf[b,c] + sf[b,h,w])
// REVERSE chunk order: first wave consumes the x tail that mean_cf left hot
// in L2. Reads evict-first (__ldcs), writes evict-first (__stcs) so this
// kernel's own streaming traffic doesn't flush the hot region.
// ---------------------------------------------------------------------------
__global__ void out_kernel(const float4* __restrict__ x, float4* __restrict__ out) {
    int chunk = gridDim.x - 1 - blockIdx.x;
    int base = chunk * 1024;                    // chunk start (plane-aligned /4)
    int plane = base >> 12;                     // (b*256 + c), constant per block
    int b = plane >> 8;
    int t = threadIdx.x;
    float cf = g_cf[plane];
    const float4* sf4 = (const float4*)g_sf + b * HW4 + (base & 4095);

    float4 v0 = __ldcs(x + base + t);
    float4 v1 = __ldcs(x + base + 256 + t);
    float4 v2 = __ldcs(x + base + 512 + t);
    float4 v3 = __ldcs(x + base + 768 + t);
    float4 f0 = sf4[t];
    float4 f1 = sf4[256 + t];
    float4 f2 = sf4[512 + t];
    float4 f3 = sf4[768 + t];

    float4 o0, o1, o2, o3;
    o0.x = v0.x * (cf + f0.x); o0.y = v0.y * (cf + f0.y);
    o0.z = v0.z * (cf + f0.z); o0.w = v0.w * (cf + f0.w);
    o1.x = v1.x * (cf + f1.x); o1.y = v1.y * (cf + f1.y);
    o1.z = v1.z * (cf + f1.z); o1.w = v1.w * (cf + f1.w);
    o2.x = v2.x * (cf + f2.x); o2.y = v2.y * (cf + f2.y);
    o2.z = v2.z * (cf + f2.z); o2.w = v2.w * (cf + f2.w);
    o3.x = v3.x * (cf + f3.x); o3.y = v3.y * (cf + f3.y);
    o3.z = v3.z * (cf + f3.z); o3.w = v3.w * (cf + f3.w);

    __stcs(out + base + t, o0);
    __stcs(out + base + 256 + t, o1);
    __stcs(out + base + 512 + t, o2);
    __stcs(out + base + 768 + t, o3);
}

extern "C" void kernel_launch(void* const* d_in, const int* in_sizes, int n_in,
                              void* d_out, int out_size) {
    const float* x    = (const float*)d_in[0];   // [16,256,128,128]
    const float* Wm   = (const float*)d_in[1];   // [256,256]
    const float* bias = (const float*)d_in[2];   // [256]
    float* out = (float*)d_out;

    mean_cf_kernel<<<1024 + 64, 64>>>((const float4*)x, Wm, bias);
    dft_stage1<<<dim3(32, B_), 256>>>();
    dft_stage2<<<dim3(32, B_), 256>>>();
    out_kernel<<<(B_ * C_ * HW4) / 1024, 256>>>((const float4*)x, (float4*)out);
}